// round 15
// baseline (speedup 1.0000x reference)
#include <cuda_runtime.h>
#include <math.h>
#include <stdint.h>

#define B_    32
#define C_    384
#define Hh    32
#define Ww    32
#define N_    1024
#define S_    4
#define NE    256
#define NHEAD 6
#define HD    64
#define EPS_  1e-5f

// ---------------- scratch (device globals; no allocation) ----------------
__device__ float g_Wr[4 * C_ * C_];  // tf32-prerounded weights, k-pair-permuted columns
__device__ float g_Q [B_*C_*N_];
__device__ float g_K [B_*C_*N_];     // tf32-rounded at GEMM epilogue
__device__ float g_V [B_*C_*N_];
__device__ float g_V2[B_*C_*N_];     // v + pe, tf32-rounded
__device__ float g_AO[B_*N_*C_];     // [b][nf][cz-permuted], tf32-rounded
__device__ float g_P [B_*C_*N_];
__device__ float g_bnS[C_ * 256];
__device__ float g_bnQ[C_ * 256];

// ---------------- generic-PTX helpers ----------------
__device__ __forceinline__ uint32_t smem_u32(const void* p) {
    uint32_t a;
    asm("{ .reg .u64 t; cvta.to.shared.u64 t, %1; cvt.u32.u64 %0, t; }" : "=r"(a) : "l"(p));
    return a;
}
__device__ __forceinline__ void cp16(uint32_t dst, const void* src) {
    asm volatile("cp.async.cg.shared.global [%0], [%1], 16;" :: "r"(dst), "l"(src) : "memory");
}
#define CP_COMMIT() asm volatile("cp.async.commit_group;" ::: "memory")
#define CP_WAIT(n)  asm volatile("cp.async.wait_group %0;" :: "n"(n) : "memory")

__device__ __forceinline__ uint32_t f2tf32(float f) {
    uint32_t u;
    asm("cvt.rna.tf32.f32 %0, %1;" : "=r"(u) : "f"(f));
    return u;
}
__device__ __forceinline__ float tf32f(float f) { return __uint_as_float(f2tf32(f)); }

__device__ __forceinline__ void mma_tf32(float c[4],
    uint32_t a0, uint32_t a1, uint32_t a2, uint32_t a3, uint32_t b0, uint32_t b1)
{
    asm volatile("mma.sync.aligned.m16n8k8.row.col.f32.tf32.tf32.f32 "
        "{%0,%1,%2,%3}, {%4,%5,%6,%7}, {%8,%9}, {%0,%1,%2,%3};"
        : "+f"(c[0]), "+f"(c[1]), "+f"(c[2]), "+f"(c[3])
        : "r"(a0), "r"(a1), "r"(a2), "r"(a3), "r"(b0), "r"(b1));
}

// pair-permutation: actual k stored at position perm8(k) within its 8-group
__device__ __forceinline__ int perm8(int k) { return (k < 4) ? (2 * k) : (2 * k - 7); }
__device__ __forceinline__ int pcol(int c) { return (c & ~7) | perm8(c & 7); }

// ---------------- K0: pre-round weights to tf32 + permute k columns ----------------
__global__ __launch_bounds__(256) void prep_weights(
    const float* __restrict__ Wq, const float* __restrict__ Wk,
    const float* __restrict__ Wv, const float* __restrict__ Wp)
{
    int u = (blockIdx.x * 256 + threadIdx.x) * 4;   // 4 consecutive output positions
    int m = u / (C_ * C_);
    int o = u - m * (C_ * C_);
    const float* src = (m == 0) ? Wq : (m == 1) ? Wk : (m == 2) ? Wv : Wp;
    float r[4];
#pragma unroll
    for (int e = 0; e < 4; e++) {
        int pos = o + e;
        int q = pos & 7;
        int k = (q & 1) ? ((q >> 1) + 4) : (q >> 1);   // inverse of perm8
        r[e] = tf32f(src[(pos & ~7) + k]);
    }
    *(float4*)(g_Wr + u) = make_float4(r[0], r[1], r[2], r[3]);
}

// ---------------- K1: QKV tf32 GEMM (NN); A permuted -> lds.64 frags ----------------
#define A_STR 40
#define B_STR 136
#define A_CH  (128 * A_STR)          // 5120
#define B_CH  (32 * B_STR)           // 4352
#define A_TOT (2 * A_CH)             // 10240
#define GS_FLOATS (A_TOT + 2 * B_CH) // 18944

__global__ __launch_bounds__(256) void qkv_mma(const float* __restrict__ x)
{
    extern __shared__ float sm[];
    float* As = sm;
    float* Bs = sm + A_TOT;
    const uint32_t sb = smem_u32(sm);

    const int t   = threadIdx.x;
    const int wid = t >> 5;
    const int lane = t & 31;
    const int g  = lane >> 2;
    const int tg = lane & 3;
    const int wm = wid & 1;
    const int wn = wid >> 1;

    const int n0 = blockIdx.x * 128;
    const int y  = blockIdx.y;
    const int b  = blockIdx.z;

    const int fam = y / 3;
    const int o0 = (y % 3) * 128;
    const float* W = g_Wr + (size_t)fam * C_ * C_;
    float* outbuf = (fam == 0) ? g_Q : (fam == 1) ? g_K : g_V;
    const float* Bp = x + (size_t)b * C_ * N_;

    float acc[4][4][4];
#pragma unroll
    for (int i = 0; i < 4; i++)
#pragma unroll
        for (int j = 0; j < 4; j++) {
            acc[i][j][0] = 0.f; acc[i][j][1] = 0.f;
            acc[i][j][2] = 0.f; acc[i][j][3] = 0.f;
        }

    auto issue = [&](int kc, int buf) {
        const int k0 = kc * 32;
        uint32_t adst = sb + (uint32_t)(buf * A_CH) * 4u;
        uint32_t bdst = sb + (uint32_t)(A_TOT + buf * B_CH) * 4u;
#pragma unroll
        for (int r = 0; r < 4; r++) {
            int i = t + r * 256;
            int row = i >> 3, c4 = (i & 7) * 4;
            cp16(adst + (uint32_t)(row * A_STR + c4) * 4u,
                 W + (size_t)(o0 + row) * C_ + k0 + c4);
        }
#pragma unroll
        for (int r = 0; r < 4; r++) {
            int i = t + r * 256;
            int row = i >> 5, c4 = (i & 31) * 4;
            cp16(bdst + (uint32_t)(row * B_STR + c4) * 4u,
                 Bp + (size_t)(k0 + row) * N_ + n0 + c4);
        }
    };

    issue(0, 0);
    CP_COMMIT();

    for (int kc = 0; kc < 12; kc++) {
        const int buf = kc & 1;
        if (kc + 1 < 12) {
            issue(kc + 1, buf ^ 1);
            CP_COMMIT();
            CP_WAIT(1);
        } else {
            CP_WAIT(0);
        }
        __syncthreads();

        const float* As_ = As + buf * A_CH;
        const float* Bs_ = Bs + buf * B_CH;

#pragma unroll
        for (int ks = 0; ks < 4; ks++) {
            const int k0 = ks * 8;
            uint32_t af[4][4], bf[4][2];
#pragma unroll
            for (int mt = 0; mt < 4; mt++) {
                const float* ap = As_ + (wm * 64 + mt * 16 + g) * A_STR + k0 + 2 * tg;
                float2 aL = *(const float2*)ap;
                float2 aH = *(const float2*)(ap + 8 * A_STR);
                af[mt][0] = __float_as_uint(aL.x);
                af[mt][2] = __float_as_uint(aL.y);
                af[mt][1] = __float_as_uint(aH.x);
                af[mt][3] = __float_as_uint(aH.y);
            }
#pragma unroll
            for (int nt = 0; nt < 4; nt++) {
                const float* bp = Bs_ + (k0 + tg) * B_STR + wn * 32 + nt * 8 + g;
                bf[nt][0] = f2tf32(bp[0]);
                bf[nt][1] = f2tf32(bp[4 * B_STR]);
            }
#pragma unroll
            for (int mt = 0; mt < 4; mt++)
#pragma unroll
                for (int nt = 0; nt < 4; nt++)
                    mma_tf32(acc[mt][nt], af[mt][0], af[mt][1], af[mt][2], af[mt][3],
                             bf[nt][0], bf[nt][1]);
        }
        __syncthreads();
    }

    const bool roundK = (fam == 1);
    float* D = outbuf + (size_t)b * C_ * N_;
#pragma unroll
    for (int mt = 0; mt < 4; mt++) {
        const int o = o0 + wm * 64 + mt * 16 + g;
#pragma unroll
        for (int nt = 0; nt < 4; nt++) {
            const int n = n0 + wn * 32 + nt * 8 + tg * 2;
            float v0 = acc[mt][nt][0], v1 = acc[mt][nt][1];
            float v2 = acc[mt][nt][2], v3 = acc[mt][nt][3];
            if (roundK) { v0 = tf32f(v0); v1 = tf32f(v1); v2 = tf32f(v2); v3 = tf32f(v3); }
            *(float2*)(D + (size_t)o * N_ + n)       = make_float2(v0, v1);
            *(float2*)(D + (size_t)(o + 8) * N_ + n) = make_float2(v2, v3);
        }
    }
}

// ---------------- K4: proj tf32 GEMM (NT), lds.64 both operands, fused BN ----------------
#define P_STR 40
#define P_CH  (128 * P_STR)          // 5120
#define PS_FLOATS (4 * P_CH)         // 20480

__global__ __launch_bounds__(256) void proj_mma()
{
    extern __shared__ float sm[];
    float* As = sm;
    float* Bs = sm + 2 * P_CH;
    const uint32_t sb = smem_u32(sm);
    __shared__ float sm_s[128][4];
    __shared__ float sm_q[128][4];

    const int t   = threadIdx.x;
    const int wid = t >> 5;
    const int lane = t & 31;
    const int g  = lane >> 2;
    const int tg = lane & 3;
    const int wm = wid & 1;
    const int wn = wid >> 1;

    const int n0 = blockIdx.x * 128;
    const int o0 = blockIdx.y * 128;
    const int b  = blockIdx.z;

    const float* Wp = g_Wr + (size_t)3 * C_ * C_;
    const float* Bp = g_AO + (size_t)b * N_ * C_;

    float acc[4][4][4];
#pragma unroll
    for (int i = 0; i < 4; i++)
#pragma unroll
        for (int j = 0; j < 4; j++) {
            acc[i][j][0] = 0.f; acc[i][j][1] = 0.f;
            acc[i][j][2] = 0.f; acc[i][j][3] = 0.f;
        }

    auto issue = [&](int kc, int buf) {
        const int k0 = kc * 32;
        uint32_t adst = sb + (uint32_t)(buf * P_CH) * 4u;
        uint32_t bdst = sb + (uint32_t)((2 + buf) * P_CH) * 4u;
#pragma unroll
        for (int r = 0; r < 4; r++) {
            int i = t + r * 256;
            int row = i >> 3, c4 = (i & 7) * 4;
            cp16(adst + (uint32_t)(row * P_STR + c4) * 4u,
                 Wp + (size_t)(o0 + row) * C_ + k0 + c4);
            cp16(bdst + (uint32_t)(row * P_STR + c4) * 4u,
                 Bp + (size_t)(n0 + row) * C_ + k0 + c4);
        }
    };

    issue(0, 0);
    CP_COMMIT();

    for (int kc = 0; kc < 12; kc++) {
        const int buf = kc & 1;
        if (kc + 1 < 12) {
            issue(kc + 1, buf ^ 1);
            CP_COMMIT();
            CP_WAIT(1);
        } else {
            CP_WAIT(0);
        }
        __syncthreads();

        const float* As_ = As + buf * P_CH;
        const float* Bs_ = Bs + buf * P_CH;

#pragma unroll
        for (int ks = 0; ks < 4; ks++) {
            const int k0 = ks * 8;
            uint32_t af[4][4], bf[4][2];
#pragma unroll
            for (int mt = 0; mt < 4; mt++) {
                const float* ap = As_ + (wm * 64 + mt * 16 + g) * P_STR + k0 + 2 * tg;
                float2 aL = *(const float2*)ap;
                float2 aH = *(const float2*)(ap + 8 * P_STR);
                af[mt][0] = __float_as_uint(aL.x);
                af[mt][2] = __float_as_uint(aL.y);
                af[mt][1] = __float_as_uint(aH.x);
                af[mt][3] = __float_as_uint(aH.y);
            }
#pragma unroll
            for (int nt = 0; nt < 4; nt++) {
                const float* bp = Bs_ + (wn * 32 + nt * 8 + g) * P_STR + k0 + 2 * tg;
                float2 bv = *(const float2*)bp;
                bf[nt][0] = __float_as_uint(bv.x);
                bf[nt][1] = __float_as_uint(bv.y);
            }
#pragma unroll
            for (int mt = 0; mt < 4; mt++)
#pragma unroll
                for (int nt = 0; nt < 4; nt++)
                    mma_tf32(acc[mt][nt], af[mt][0], af[mt][1], af[mt][2], af[mt][3],
                             bf[nt][0], bf[nt][1]);
        }
        __syncthreads();
    }

    float* D = g_P + (size_t)b * C_ * N_;
#pragma unroll
    for (int mt = 0; mt < 4; mt++) {
        const int o = o0 + wm * 64 + mt * 16 + g;
        float s_lo = 0.f, s_hi = 0.f, q_lo = 0.f, q_hi = 0.f;
#pragma unroll
        for (int nt = 0; nt < 4; nt++) {
            const int n = n0 + wn * 32 + nt * 8 + tg * 2;
            float v0 = acc[mt][nt][0], v1 = acc[mt][nt][1];
            float v2 = acc[mt][nt][2], v3 = acc[mt][nt][3];
            *(float2*)(D + (size_t)o * N_ + n)       = make_float2(v0, v1);
            *(float2*)(D + (size_t)(o + 8) * N_ + n) = make_float2(v2, v3);
            s_lo += v0 + v1; q_lo += v0 * v0 + v1 * v1;
            s_hi += v2 + v3; q_hi += v2 * v2 + v3 * v3;
        }
        s_lo += __shfl_xor_sync(0xffffffffu, s_lo, 1);
        s_lo += __shfl_xor_sync(0xffffffffu, s_lo, 2);
        q_lo += __shfl_xor_sync(0xffffffffu, q_lo, 1);
        q_lo += __shfl_xor_sync(0xffffffffu, q_lo, 2);
        s_hi += __shfl_xor_sync(0xffffffffu, s_hi, 1);
        s_hi += __shfl_xor_sync(0xffffffffu, s_hi, 2);
        q_hi += __shfl_xor_sync(0xffffffffu, q_hi, 1);
        q_hi += __shfl_xor_sync(0xffffffffu, q_hi, 2);
        if (tg == 0) {
            int rl = wm * 64 + mt * 16 + g;
            sm_s[rl][wn] = s_lo; sm_q[rl][wn] = q_lo;
            sm_s[rl + 8][wn] = s_hi; sm_q[rl + 8][wn] = q_hi;
        }
    }
    __syncthreads();
    if (t < 128) {
        float s = sm_s[t][0] + sm_s[t][1] + sm_s[t][2] + sm_s[t][3];
        float q = sm_q[t][0] + sm_q[t][1] + sm_q[t][2] + sm_q[t][3];
        int slice = b * 8 + blockIdx.x;
        g_bnS[(size_t)(o0 + t) * 256 + slice] = s;
        g_bnQ[(size_t)(o0 + t) * 256 + slice] = q;
    }
}

// ---------------- K2: depthwise 3x3 PE + add; output tf32-rounded ----------------
__global__ __launch_bounds__(256) void dwconv_smem(const float* __restrict__ Wpe)
{
    __shared__ float tile[34 * 34];
    __shared__ float wsh[9];
    const int bc = blockIdx.x;
    const int c  = bc % C_;
    const float* vb = g_V + (size_t)bc * N_;
    const int t = threadIdx.x;
    if (t < 9) wsh[t] = Wpe[c * 9 + t];
    for (int i = t; i < 34 * 34; i += 256) {
        int r = i / 34 - 1, col = i % 34 - 1;
        tile[i] = (r >= 0 && r < 32 && col >= 0 && col < 32) ? vb[r * 32 + col] : 0.f;
    }
    __syncthreads();
    const float w0 = wsh[0], w1 = wsh[1], w2 = wsh[2];
    const float w3 = wsh[3], w4 = wsh[4], w5 = wsh[5];
    const float w6 = wsh[6], w7 = wsh[7], w8 = wsh[8];
    float* outp = g_V2 + (size_t)bc * N_;
#pragma unroll
    for (int j = 0; j < 4; j++) {
        int n = t + j * 256;
        int hh = n >> 5, ww = n & 31;
        const float* tp = &tile[hh * 34 + ww];
        float s = w0 * tp[0]  + w1 * tp[1]  + w2 * tp[2]
                + w3 * tp[34] + w4 * tp[35] + w5 * tp[36]
                + w6 * tp[68] + w7 * tp[69] + w8 * tp[70];
        outp[n] = tf32f(tp[35] + s);
    }
}

// ---------------- K3: attention — FA2, 4 chunks, double-buffered ----------------
#define KS2 72
#define VS2 72
#define CHF 9216
#define ATT_FLOATS 18432

__global__ __launch_bounds__(128, 3) void attn_flash()
{
    extern __shared__ float sm[];
    const uint32_t sb = smem_u32(sm);

    const int nt = blockIdx.x;
    const int h  = blockIdx.y;
    const int be = blockIdx.z;
    const int b  = be >> 2;
    const int sP = be & 3;
    const int n0 = nt * 64;

    const int t = threadIdx.x;
    const int wid = t >> 5, lane = t & 31;
    const int g = lane >> 2, tg = lane & 3;

    const float* Qg = g_Q  + ((size_t)b * C_ + h * HD) * N_ + sP * NE;
    const float* Kg = g_K  + ((size_t)b * C_ + h * HD) * N_ + sP * NE;
    const float* Vg = g_V2 + ((size_t)b * C_ + h * HD) * N_ + sP * NE;

    auto issue_chunk = [&](int ck, int buf) {
        uint32_t kb = sb + (uint32_t)(buf * CHF) * 4u;
        uint32_t vb = kb + 4608u * 4u;
#pragma unroll
        for (int j = 0; j < 8; j++) {
            int u = t + j * 128;
            int d = u >> 4, m4 = (u & 15) * 4;
            cp16(kb + (uint32_t)(d * KS2 + m4) * 4u,
                 Kg + (size_t)d * N_ + ck * 64 + m4);
        }
#pragma unroll
        for (int j = 0; j < 8; j++) {
            int u = t + j * 128;
            int d = u >> 4, m4 = (u & 15) * 4;
            cp16(vb + (uint32_t)(d * VS2 + m4) * 4u,
                 Vg + (size_t)d * N_ + ck * 64 + m4);
        }
        CP_COMMIT();
    };

    issue_chunk(0, 0);

    uint32_t qa[8][4];
    const int c0 = n0 + wid * 16 + g;
#pragma unroll
    for (int ks = 0; ks < 8; ks++) {
        int d0 = ks * 8 + tg, d1 = d0 + 4;
        qa[ks][0] = f2tf32(0.125f * Qg[(size_t)d0 * N_ + c0]);
        qa[ks][1] = f2tf32(0.125f * Qg[(size_t)d0 * N_ + c0 + 8]);
        qa[ks][2] = f2tf32(0.125f * Qg[(size_t)d1 * N_ + c0]);
        qa[ks][3] = f2tf32(0.125f * Qg[(size_t)d1 * N_ + c0 + 8]);
    }

    float rm1 = -1e30f, rm2 = -1e30f;
    float rs1 = 0.f, rs2 = 0.f;

    float av[8][4];
#pragma unroll
    for (int i = 0; i < 8; i++) {
        av[i][0] = 0.f; av[i][1] = 0.f; av[i][2] = 0.f; av[i][3] = 0.f;
    }

    for (int ck = 0; ck < 4; ck++) {
        const int buf = ck & 1;
        if (ck + 1 < 4) {
            issue_chunk(ck + 1, buf ^ 1);
            CP_WAIT(1);
        } else {
            CP_WAIT(0);
        }
        __syncthreads();

        const float* Ks = sm + buf * CHF;
        const float* Vs = Ks + 4608;

        float acc[8][4];
#pragma unroll
        for (int i = 0; i < 8; i++) {
            acc[i][0] = 0.f; acc[i][1] = 0.f; acc[i][2] = 0.f; acc[i][3] = 0.f;
        }
#pragma unroll
        for (int ks = 0; ks < 8; ks++) {
#pragma unroll
            for (int nf = 0; nf < 8; nf++) {
                const float* bp = Ks + (ks * 8 + tg) * KS2 + nf * 8 + g;
                mma_tf32(acc[nf], qa[ks][0], qa[ks][1], qa[ks][2], qa[ks][3],
                         __float_as_uint(bp[0]), __float_as_uint(bp[4 * KS2]));
            }
        }

        float m1 = -1e30f, m2 = -1e30f;
#pragma unroll
        for (int nf = 0; nf < 8; nf++) {
            m1 = fmaxf(m1, fmaxf(acc[nf][0], acc[nf][1]));
            m2 = fmaxf(m2, fmaxf(acc[nf][2], acc[nf][3]));
        }
        m1 = fmaxf(m1, __shfl_xor_sync(0xffffffffu, m1, 1));
        m1 = fmaxf(m1, __shfl_xor_sync(0xffffffffu, m1, 2));
        m2 = fmaxf(m2, __shfl_xor_sync(0xffffffffu, m2, 1));
        m2 = fmaxf(m2, __shfl_xor_sync(0xffffffffu, m2, 2));

        float nm1 = fmaxf(rm1, m1);
        float nm2 = fmaxf(rm2, m2);
        float corr1 = __expf(rm1 - nm1);
        float corr2 = __expf(rm2 - nm2);

        float s1 = 0.f, s2 = 0.f;
#pragma unroll
        for (int nf = 0; nf < 8; nf++) {
            acc[nf][0] = __expf(acc[nf][0] - nm1);
            acc[nf][1] = __expf(acc[nf][1] - nm1);
            acc[nf][2] = __expf(acc[nf][2] - nm2);
            acc[nf][3] = __expf(acc[nf][3] - nm2);
            s1 += acc[nf][0] + acc[nf][1];
            s2 += acc[nf][2] + acc[nf][3];
        }
        s1 += __shfl_xor_sync(0xffffffffu, s1, 1);
        s1 += __shfl_xor_sync(0xffffffffu, s1, 2);
        s2 += __shfl_xor_sync(0xffffffffu, s2, 1);
        s2 += __shfl_xor_sync(0xffffffffu, s2, 2);

        rs1 = rs1 * corr1 + s1;
        rs2 = rs2 * corr2 + s2;
        rm1 = nm1;
        rm2 = nm2;

#pragma unroll
        for (int nf = 0; nf < 8; nf++) {
            av[nf][0] *= corr1; av[nf][1] *= corr1;
            av[nf][2] *= corr2; av[nf][3] *= corr2;
        }

#pragma unroll
        for (int ks2 = 0; ks2 < 8; ks2++) {
            uint32_t a0 = f2tf32(acc[ks2][0]);
            uint32_t a1 = f2tf32(acc[ks2][2]);
            uint32_t a2 = f2tf32(acc[ks2][1]);
            uint32_t a3 = f2tf32(acc[ks2][3]);
#pragma unroll
            for (int nf2 = 0; nf2 < 8; nf2++) {
                const float2 bv = *(const float2*)(Vs + (nf2 * 8 + g) * VS2
                                                   + ks2 * 8 + 2 * tg);
                mma_tf32(av[nf2], a0, a1, a2, a3,
                         __float_as_uint(bv.x), __float_as_uint(bv.y));
            }
        }
        __syncthreads();
    }

    // ---- normalize + store (cz pair-permuted for proj lds.64) ----
    const float inv1 = 1.f / rs1;
    const float inv2 = 1.f / rs2;
    float* AOb = g_AO + (size_t)b * N_ * C_;
    const int r1 = wid * 16 + g;
#pragma unroll
    for (int nf2 = 0; nf2 < 8; nf2++) {
#pragma unroll
        for (int e = 0; e < 4; e++) {
            int d = nf2 * 8 + 2 * tg + (e & 1);
            int rr = r1 + ((e >> 1) ? 8 : 0);
            float v = tf32f(av[nf2][e] * ((e >> 1) ? inv2 : inv1));
            int n = n0 + rr;
            unsigned lin = (unsigned)(h * HD + d) * NE + (unsigned)n;
            unsigned ne2 = lin / C_;
            unsigned cz  = lin - ne2 * C_;
            unsigned nf3 = ne2 * S_ + (unsigned)sP;
            AOb[(size_t)nf3 * C_ + (unsigned)pcol((int)cz)] = v;
        }
    }
}

// ---------------- K6: BN finalize + residual + normalize (fused) ----------------
__global__ __launch_bounds__(256) void final_kernel(
    const float* __restrict__ x,
    const float* __restrict__ gamma,
    const float* __restrict__ beta,
    float* __restrict__ out)
{
    __shared__ float sS[8], sQ[8];
    __shared__ float sMu, sRs;
    const int t = threadIdx.x;
    const int bc = blockIdx.x;
    const int c = bc % C_;

    float s = g_bnS[(size_t)c * 256 + t];
    float q = g_bnQ[(size_t)c * 256 + t];
#pragma unroll
    for (int off = 16; off > 0; off >>= 1) {
        s += __shfl_xor_sync(0xffffffffu, s, off);
        q += __shfl_xor_sync(0xffffffffu, q, off);
    }
    if ((t & 31) == 0) { sS[t >> 5] = s; sQ[t >> 5] = q; }
    __syncthreads();
    if (t == 0) {
        float ss = ((sS[0] + sS[1]) + (sS[2] + sS[3])) + ((sS[4] + sS[5]) + (sS[6] + sS[7]));
        float qq = ((sQ[0] + sQ[1]) + (sQ[2] + sQ[3])) + ((sQ[4] + sQ[5]) + (sQ[6] + sQ[7]));
        float inv_n = 1.f / (float)(B_ * N_);
        float mu  = ss * inv_n;
        float var = qq * inv_n - mu * mu;
        sMu = mu;
        sRs = rsqrtf(var + EPS_);
    }
    __syncthreads();

    const float ga = gamma[c], be = beta[c], mu = sMu, rs = sRs;
    size_t base = (size_t)bc * N_ + t * 4;
    float4 v  = *(const float4*)(g_P + base);
    float4 xv = *(const float4*)(x + base);
    float4 r;
    r.x = xv.x + ga * (v.x - mu) * rs + be;
    r.y = xv.y + ga * (v.y - mu) * rs + be;
    r.z = xv.z + ga * (v.z - mu) * rs + be;
    r.w = xv.w + ga * (v.w - mu) * rs + be;
    *(float4*)(out + base) = r;
}

// ---------------- launch ----------------
extern "C" void kernel_launch(void* const* d_in, const int* in_sizes, int n_in,
                              void* d_out, int out_size)
{
    const float* x     = (const float*)d_in[0];
    const float* Wq    = (const float*)d_in[1];
    const float* Wk    = (const float*)d_in[2];
    const float* Wv    = (const float*)d_in[3];
    const float* Wpe   = (const float*)d_in[4];
    const float* Wproj = (const float*)d_in[5];
    const float* gamma = (const float*)d_in[6];
    const float* beta  = (const float*)d_in[7];
    float* out = (float*)d_out;

    static bool attr_set = false;
    if (!attr_set) {
        cudaFuncSetAttribute(qkv_mma, cudaFuncAttributeMaxDynamicSharedMemorySize,
                             GS_FLOATS * (int)sizeof(float));
        cudaFuncSetAttribute(proj_mma, cudaFuncAttributeMaxDynamicSharedMemorySize,
                             PS_FLOATS * (int)sizeof(float));
        cudaFuncSetAttribute(attn_flash, cudaFuncAttributeMaxDynamicSharedMemorySize,
                             ATT_FLOATS * (int)sizeof(float));
        attr_set = true;
    }

    prep_weights<<<(4 * C_ * C_) / 1024, 256>>>(Wq, Wk, Wv, Wproj);

    qkv_mma<<<dim3(N_ / 128, 9, B_), 256, GS_FLOATS * sizeof(float)>>>(x);

    dwconv_smem<<<B_ * C_, 256>>>(Wpe);

    attn_flash<<<dim3(4, NHEAD, 128), 128, ATT_FLOATS * sizeof(float)>>>();

    proj_mma<<<dim3(N_ / 128, C_ / 128, B_), 256, PS_FLOATS * sizeof(float)>>>();

    final_kernel<<<B_ * C_, 256>>>(x, gamma, beta, out);
}

// round 16
// speedup vs baseline: 1.5022x; 1.5022x over previous
#include <cuda_runtime.h>
#include <math.h>
#include <stdint.h>

#define B_    32
#define C_    384
#define Hh    32
#define Ww    32
#define N_    1024
#define S_    4
#define NE    256
#define NHEAD 6
#define HD    64
#define EPS_  1e-5f

// ---------------- scratch (device globals; no allocation) ----------------
__device__ float g_Wr[4 * C_ * C_];  // tf32-prerounded weights
__device__ float g_Q [B_*C_*N_];
__device__ float g_K [B_*C_*N_];     // tf32-rounded at GEMM epilogue
__device__ float g_V [B_*C_*N_];
__device__ float g_V2[B_*C_*N_];     // v + pe, tf32-rounded
__device__ float g_AO[B_*N_*C_];     // [b][nf][cz], tf32-rounded
__device__ float g_P [B_*C_*N_];
__device__ float g_bnS[C_ * 256];
__device__ float g_bnQ[C_ * 256];

// ---------------- generic-PTX helpers ----------------
__device__ __forceinline__ uint32_t smem_u32(const void* p) {
    uint32_t a;
    asm("{ .reg .u64 t; cvta.to.shared.u64 t, %1; cvt.u32.u64 %0, t; }" : "=r"(a) : "l"(p));
    return a;
}
__device__ __forceinline__ void cp16(uint32_t dst, const void* src) {
    asm volatile("cp.async.cg.shared.global [%0], [%1], 16;" :: "r"(dst), "l"(src) : "memory");
}
#define CP_COMMIT() asm volatile("cp.async.commit_group;" ::: "memory")
#define CP_WAIT(n)  asm volatile("cp.async.wait_group %0;" :: "n"(n) : "memory")

__device__ __forceinline__ uint32_t f2tf32(float f) {
    uint32_t u;
    asm("cvt.rna.tf32.f32 %0, %1;" : "=r"(u) : "f"(f));
    return u;
}
__device__ __forceinline__ float tf32f(float f) { return __uint_as_float(f2tf32(f)); }

__device__ __forceinline__ void mma_tf32(float c[4],
    uint32_t a0, uint32_t a1, uint32_t a2, uint32_t a3, uint32_t b0, uint32_t b1)
{
    asm volatile("mma.sync.aligned.m16n8k8.row.col.f32.tf32.tf32.f32 "
        "{%0,%1,%2,%3}, {%4,%5,%6,%7}, {%8,%9}, {%0,%1,%2,%3};"
        : "+f"(c[0]), "+f"(c[1]), "+f"(c[2]), "+f"(c[3])
        : "r"(a0), "r"(a1), "r"(a2), "r"(a3), "r"(b0), "r"(b1));
}

// ---------------- K0: pre-round weights to tf32 ----------------
__global__ __launch_bounds__(256) void prep_weights(
    const float* __restrict__ Wq, const float* __restrict__ Wk,
    const float* __restrict__ Wv, const float* __restrict__ Wp)
{
    int u = (blockIdx.x * 256 + threadIdx.x) * 4;
    int m = u / (C_ * C_);
    int o = u - m * (C_ * C_);
    const float* src = (m == 0) ? Wq : (m == 1) ? Wk : (m == 2) ? Wv : Wp;
    float4 v = *(const float4*)(src + o);
    v.x = tf32f(v.x); v.y = tf32f(v.y); v.z = tf32f(v.z); v.w = tf32f(v.w);
    *(float4*)(g_Wr + u) = v;
}

// ---------------- K1: QKV tf32 GEMM (NN) ----------------
#define A_STR 36
#define B_STR 136
#define A_CH  (128 * A_STR)
#define B_CH  (32 * B_STR)
#define A_TOT (2 * A_CH)
#define GS_FLOATS (A_TOT + 2 * B_CH)

__global__ __launch_bounds__(256) void qkv_mma(const float* __restrict__ x)
{
    extern __shared__ float sm[];
    float* As = sm;
    float* Bs = sm + A_TOT;
    const uint32_t sb = smem_u32(sm);

    const int t   = threadIdx.x;
    const int wid = t >> 5;
    const int lane = t & 31;
    const int g  = lane >> 2;
    const int tg = lane & 3;
    const int wm = wid & 1;
    const int wn = wid >> 1;

    const int n0 = blockIdx.x * 128;
    const int y  = blockIdx.y;
    const int b  = blockIdx.z;

    const int fam = y / 3;
    const int o0 = (y % 3) * 128;
    const float* W = g_Wr + (size_t)fam * C_ * C_;
    float* outbuf = (fam == 0) ? g_Q : (fam == 1) ? g_K : g_V;
    const float* Bp = x + (size_t)b * C_ * N_;

    float acc[4][4][4];
#pragma unroll
    for (int i = 0; i < 4; i++)
#pragma unroll
        for (int j = 0; j < 4; j++) {
            acc[i][j][0] = 0.f; acc[i][j][1] = 0.f;
            acc[i][j][2] = 0.f; acc[i][j][3] = 0.f;
        }

    auto issue = [&](int kc, int buf) {
        const int k0 = kc * 32;
        uint32_t adst = sb + (uint32_t)(buf * A_CH) * 4u;
        uint32_t bdst = sb + (uint32_t)(A_TOT + buf * B_CH) * 4u;
#pragma unroll
        for (int r = 0; r < 4; r++) {
            int i = t + r * 256;
            int row = i >> 3, c4 = (i & 7) * 4;
            cp16(adst + (uint32_t)(row * A_STR + c4) * 4u,
                 W + (size_t)(o0 + row) * C_ + k0 + c4);
        }
#pragma unroll
        for (int r = 0; r < 4; r++) {
            int i = t + r * 256;
            int row = i >> 5, c4 = (i & 31) * 4;
            cp16(bdst + (uint32_t)(row * B_STR + c4) * 4u,
                 Bp + (size_t)(k0 + row) * N_ + n0 + c4);
        }
    };

    issue(0, 0);
    CP_COMMIT();

    for (int kc = 0; kc < 12; kc++) {
        const int buf = kc & 1;
        if (kc + 1 < 12) {
            issue(kc + 1, buf ^ 1);
            CP_COMMIT();
            CP_WAIT(1);
        } else {
            CP_WAIT(0);
        }
        __syncthreads();

        const float* As_ = As + buf * A_CH;
        const float* Bs_ = Bs + buf * B_CH;

#pragma unroll
        for (int ks = 0; ks < 4; ks++) {
            const int k0 = ks * 8;
            uint32_t af[4][4], bf[4][2];
#pragma unroll
            for (int mt = 0; mt < 4; mt++) {
                const float* ap = As_ + (wm * 64 + mt * 16 + g) * A_STR + k0 + tg;
                af[mt][0] = __float_as_uint(ap[0]);
                af[mt][1] = __float_as_uint(ap[8 * A_STR]);
                af[mt][2] = __float_as_uint(ap[4]);
                af[mt][3] = __float_as_uint(ap[8 * A_STR + 4]);
            }
#pragma unroll
            for (int nt = 0; nt < 4; nt++) {
                const float* bp = Bs_ + (k0 + tg) * B_STR + wn * 32 + nt * 8 + g;
                bf[nt][0] = f2tf32(bp[0]);
                bf[nt][1] = f2tf32(bp[4 * B_STR]);
            }
#pragma unroll
            for (int mt = 0; mt < 4; mt++)
#pragma unroll
                for (int nt = 0; nt < 4; nt++)
                    mma_tf32(acc[mt][nt], af[mt][0], af[mt][1], af[mt][2], af[mt][3],
                             bf[nt][0], bf[nt][1]);
        }
        __syncthreads();
    }

    const bool roundK = (fam == 1);
    float* D = outbuf + (size_t)b * C_ * N_;
#pragma unroll
    for (int mt = 0; mt < 4; mt++) {
        const int o = o0 + wm * 64 + mt * 16 + g;
#pragma unroll
        for (int nt = 0; nt < 4; nt++) {
            const int n = n0 + wn * 32 + nt * 8 + tg * 2;
            float v0 = acc[mt][nt][0], v1 = acc[mt][nt][1];
            float v2 = acc[mt][nt][2], v3 = acc[mt][nt][3];
            if (roundK) { v0 = tf32f(v0); v1 = tf32f(v1); v2 = tf32f(v2); v3 = tf32f(v3); }
            *(float2*)(D + (size_t)o * N_ + n)       = make_float2(v0, v1);
            *(float2*)(D + (size_t)(o + 8) * N_ + n) = make_float2(v2, v3);
        }
    }
}

// ---------------- K4: proj tf32 GEMM (NT), CVT-free, fused BN partials ----------------
#define P_CH (128 * A_STR)
#define PS_FLOATS (4 * P_CH)

__global__ __launch_bounds__(256) void proj_mma()
{
    extern __shared__ float sm[];
    float* As = sm;
    float* Bs = sm + 2 * P_CH;
    const uint32_t sb = smem_u32(sm);
    __shared__ float sm_s[128][4];
    __shared__ float sm_q[128][4];

    const int t   = threadIdx.x;
    const int wid = t >> 5;
    const int lane = t & 31;
    const int g  = lane >> 2;
    const int tg = lane & 3;
    const int wm = wid & 1;
    const int wn = wid >> 1;

    const int n0 = blockIdx.x * 128;
    const int o0 = blockIdx.y * 128;
    const int b  = blockIdx.z;

    const float* Wp = g_Wr + (size_t)3 * C_ * C_;
    const float* Bp = g_AO + (size_t)b * N_ * C_;

    float acc[4][4][4];
#pragma unroll
    for (int i = 0; i < 4; i++)
#pragma unroll
        for (int j = 0; j < 4; j++) {
            acc[i][j][0] = 0.f; acc[i][j][1] = 0.f;
            acc[i][j][2] = 0.f; acc[i][j][3] = 0.f;
        }

    auto issue = [&](int kc, int buf) {
        const int k0 = kc * 32;
        uint32_t adst = sb + (uint32_t)(buf * P_CH) * 4u;
        uint32_t bdst = sb + (uint32_t)((2 + buf) * P_CH) * 4u;
#pragma unroll
        for (int r = 0; r < 4; r++) {
            int i = t + r * 256;
            int row = i >> 3, c4 = (i & 7) * 4;
            cp16(adst + (uint32_t)(row * A_STR + c4) * 4u,
                 Wp + (size_t)(o0 + row) * C_ + k0 + c4);
            cp16(bdst + (uint32_t)(row * A_STR + c4) * 4u,
                 Bp + (size_t)(n0 + row) * C_ + k0 + c4);
        }
    };

    issue(0, 0);
    CP_COMMIT();

    for (int kc = 0; kc < 12; kc++) {
        const int buf = kc & 1;
        if (kc + 1 < 12) {
            issue(kc + 1, buf ^ 1);
            CP_COMMIT();
            CP_WAIT(1);
        } else {
            CP_WAIT(0);
        }
        __syncthreads();

        const float* As_ = As + buf * P_CH;
        const float* Bs_ = Bs + buf * P_CH;

#pragma unroll
        for (int ks = 0; ks < 4; ks++) {
            const int k0 = ks * 8;
            uint32_t af[4][4], bf[4][2];
#pragma unroll
            for (int mt = 0; mt < 4; mt++) {
                const float* ap = As_ + (wm * 64 + mt * 16 + g) * A_STR + k0 + tg;
                af[mt][0] = __float_as_uint(ap[0]);
                af[mt][1] = __float_as_uint(ap[8 * A_STR]);
                af[mt][2] = __float_as_uint(ap[4]);
                af[mt][3] = __float_as_uint(ap[8 * A_STR + 4]);
            }
#pragma unroll
            for (int nt = 0; nt < 4; nt++) {
                const float* bp = Bs_ + (wn * 32 + nt * 8 + g) * A_STR + k0 + tg;
                bf[nt][0] = __float_as_uint(bp[0]);
                bf[nt][1] = __float_as_uint(bp[4]);
            }
#pragma unroll
            for (int mt = 0; mt < 4; mt++)
#pragma unroll
                for (int nt = 0; nt < 4; nt++)
                    mma_tf32(acc[mt][nt], af[mt][0], af[mt][1], af[mt][2], af[mt][3],
                             bf[nt][0], bf[nt][1]);
        }
        __syncthreads();
    }

    float* D = g_P + (size_t)b * C_ * N_;
#pragma unroll
    for (int mt = 0; mt < 4; mt++) {
        const int o = o0 + wm * 64 + mt * 16 + g;
        float s_lo = 0.f, s_hi = 0.f, q_lo = 0.f, q_hi = 0.f;
#pragma unroll
        for (int nt = 0; nt < 4; nt++) {
            const int n = n0 + wn * 32 + nt * 8 + tg * 2;
            float v0 = acc[mt][nt][0], v1 = acc[mt][nt][1];
            float v2 = acc[mt][nt][2], v3 = acc[mt][nt][3];
            *(float2*)(D + (size_t)o * N_ + n)       = make_float2(v0, v1);
            *(float2*)(D + (size_t)(o + 8) * N_ + n) = make_float2(v2, v3);
            s_lo += v0 + v1; q_lo += v0 * v0 + v1 * v1;
            s_hi += v2 + v3; q_hi += v2 * v2 + v3 * v3;
        }
        s_lo += __shfl_xor_sync(0xffffffffu, s_lo, 1);
        s_lo += __shfl_xor_sync(0xffffffffu, s_lo, 2);
        q_lo += __shfl_xor_sync(0xffffffffu, q_lo, 1);
        q_lo += __shfl_xor_sync(0xffffffffu, q_lo, 2);
        s_hi += __shfl_xor_sync(0xffffffffu, s_hi, 1);
        s_hi += __shfl_xor_sync(0xffffffffu, s_hi, 2);
        q_hi += __shfl_xor_sync(0xffffffffu, q_hi, 1);
        q_hi += __shfl_xor_sync(0xffffffffu, q_hi, 2);
        if (tg == 0) {
            int rl = wm * 64 + mt * 16 + g;
            sm_s[rl][wn] = s_lo; sm_q[rl][wn] = q_lo;
            sm_s[rl + 8][wn] = s_hi; sm_q[rl + 8][wn] = q_hi;
        }
    }
    __syncthreads();
    if (t < 128) {
        float s = sm_s[t][0] + sm_s[t][1] + sm_s[t][2] + sm_s[t][3];
        float q = sm_q[t][0] + sm_q[t][1] + sm_q[t][2] + sm_q[t][3];
        int slice = b * 8 + blockIdx.x;
        g_bnS[(size_t)(o0 + t) * 256 + slice] = s;
        g_bnQ[(size_t)(o0 + t) * 256 + slice] = q;
    }
}

// ---------------- K2: depthwise 3x3 PE + add; output tf32-rounded ----------------
__global__ __launch_bounds__(256) void dwconv_smem(const float* __restrict__ Wpe)
{
    __shared__ float tile[34 * 34];
    __shared__ float wsh[9];
    const int bc = blockIdx.x;
    const int c  = bc % C_;
    const float* vb = g_V + (size_t)bc * N_;
    const int t = threadIdx.x;
    if (t < 9) wsh[t] = Wpe[c * 9 + t];
    for (int i = t; i < 34 * 34; i += 256) {
        int r = i / 34 - 1, col = i % 34 - 1;
        tile[i] = (r >= 0 && r < 32 && col >= 0 && col < 32) ? vb[r * 32 + col] : 0.f;
    }
    __syncthreads();
    const float w0 = wsh[0], w1 = wsh[1], w2 = wsh[2];
    const float w3 = wsh[3], w4 = wsh[4], w5 = wsh[5];
    const float w6 = wsh[6], w7 = wsh[7], w8 = wsh[8];
    float* outp = g_V2 + (size_t)bc * N_;
#pragma unroll
    for (int j = 0; j < 4; j++) {
        int n = t + j * 256;
        int hh = n >> 5, ww = n & 31;
        const float* tp = &tile[hh * 34 + ww];
        float s = w0 * tp[0]  + w1 * tp[1]  + w2 * tp[2]
                + w3 * tp[34] + w4 * tp[35] + w5 * tp[36]
                + w6 * tp[68] + w7 * tp[69] + w8 * tp[70];
        outp[n] = tf32f(tp[35] + s);
    }
}

// ---------------- K3: attention — FA2, 4 chunks of 64, double-buffered, occ 3 ----------------
#define KS2 72
#define VS2 72
#define CHF 9216
#define ATT_FLOATS 18432

__global__ __launch_bounds__(128, 3) void attn_flash()
{
    extern __shared__ float sm[];
    const uint32_t sb = smem_u32(sm);

    const int nt = blockIdx.x;
    const int h  = blockIdx.y;
    const int be = blockIdx.z;
    const int b  = be >> 2;
    const int sP = be & 3;
    const int n0 = nt * 64;

    const int t = threadIdx.x;
    const int wid = t >> 5, lane = t & 31;
    const int g = lane >> 2, tg = lane & 3;

    const float* Qg = g_Q  + ((size_t)b * C_ + h * HD) * N_ + sP * NE;
    const float* Kg = g_K  + ((size_t)b * C_ + h * HD) * N_ + sP * NE;
    const float* Vg = g_V2 + ((size_t)b * C_ + h * HD) * N_ + sP * NE;

    auto issue_chunk = [&](int ck, int buf) {
        uint32_t kb = sb + (uint32_t)(buf * CHF) * 4u;
        uint32_t vb = kb + 4608u * 4u;
#pragma unroll
        for (int j = 0; j < 8; j++) {
            int u = t + j * 128;
            int d = u >> 4, m4 = (u & 15) * 4;
            cp16(kb + (uint32_t)(d * KS2 + m4) * 4u,
                 Kg + (size_t)d * N_ + ck * 64 + m4);
        }
#pragma unroll
        for (int j = 0; j < 8; j++) {
            int u = t + j * 128;
            int d = u >> 4, m4 = (u & 15) * 4;
            cp16(vb + (uint32_t)(d * VS2 + m4) * 4u,
                 Vg + (size_t)d * N_ + ck * 64 + m4);
        }
        CP_COMMIT();
    };

    issue_chunk(0, 0);

    uint32_t qa[8][4];
    const int c0 = n0 + wid * 16 + g;
#pragma unroll
    for (int ks = 0; ks < 8; ks++) {
        int d0 = ks * 8 + tg, d1 = d0 + 4;
        qa[ks][0] = f2tf32(0.125f * Qg[(size_t)d0 * N_ + c0]);
        qa[ks][1] = f2tf32(0.125f * Qg[(size_t)d0 * N_ + c0 + 8]);
        qa[ks][2] = f2tf32(0.125f * Qg[(size_t)d1 * N_ + c0]);
        qa[ks][3] = f2tf32(0.125f * Qg[(size_t)d1 * N_ + c0 + 8]);
    }

    float rm1 = -1e30f, rm2 = -1e30f;
    float rs1 = 0.f, rs2 = 0.f;

    float av[8][4];
#pragma unroll
    for (int i = 0; i < 8; i++) {
        av[i][0] = 0.f; av[i][1] = 0.f; av[i][2] = 0.f; av[i][3] = 0.f;
    }

    for (int ck = 0; ck < 4; ck++) {
        const int buf = ck & 1;
        if (ck + 1 < 4) {
            issue_chunk(ck + 1, buf ^ 1);
            CP_WAIT(1);
        } else {
            CP_WAIT(0);
        }
        __syncthreads();

        const float* Ks = sm + buf * CHF;
        const float* Vs = Ks + 4608;

        float acc[8][4];
#pragma unroll
        for (int i = 0; i < 8; i++) {
            acc[i][0] = 0.f; acc[i][1] = 0.f; acc[i][2] = 0.f; acc[i][3] = 0.f;
        }
#pragma unroll
        for (int ks = 0; ks < 8; ks++) {
#pragma unroll
            for (int nf = 0; nf < 8; nf++) {
                const float* bp = Ks + (ks * 8 + tg) * KS2 + nf * 8 + g;
                mma_tf32(acc[nf], qa[ks][0], qa[ks][1], qa[ks][2], qa[ks][3],
                         __float_as_uint(bp[0]), __float_as_uint(bp[4 * KS2]));
            }
        }

        float m1 = -1e30f, m2 = -1e30f;
#pragma unroll
        for (int nf = 0; nf < 8; nf++) {
            m1 = fmaxf(m1, fmaxf(acc[nf][0], acc[nf][1]));
            m2 = fmaxf(m2, fmaxf(acc[nf][2], acc[nf][3]));
        }
        m1 = fmaxf(m1, __shfl_xor_sync(0xffffffffu, m1, 1));
        m1 = fmaxf(m1, __shfl_xor_sync(0xffffffffu, m1, 2));
        m2 = fmaxf(m2, __shfl_xor_sync(0xffffffffu, m2, 1));
        m2 = fmaxf(m2, __shfl_xor_sync(0xffffffffu, m2, 2));

        float nm1 = fmaxf(rm1, m1);
        float nm2 = fmaxf(rm2, m2);
        float corr1 = __expf(rm1 - nm1);
        float corr2 = __expf(rm2 - nm2);

        float s1 = 0.f, s2 = 0.f;
#pragma unroll
        for (int nf = 0; nf < 8; nf++) {
            acc[nf][0] = __expf(acc[nf][0] - nm1);
            acc[nf][1] = __expf(acc[nf][1] - nm1);
            acc[nf][2] = __expf(acc[nf][2] - nm2);
            acc[nf][3] = __expf(acc[nf][3] - nm2);
            s1 += acc[nf][0] + acc[nf][1];
            s2 += acc[nf][2] + acc[nf][3];
        }
        s1 += __shfl_xor_sync(0xffffffffu, s1, 1);
        s1 += __shfl_xor_sync(0xffffffffu, s1, 2);
        s2 += __shfl_xor_sync(0xffffffffu, s2, 1);
        s2 += __shfl_xor_sync(0xffffffffu, s2, 2);

        rs1 = rs1 * corr1 + s1;
        rs2 = rs2 * corr2 + s2;
        rm1 = nm1;
        rm2 = nm2;

#pragma unroll
        for (int nf = 0; nf < 8; nf++) {
            av[nf][0] *= corr1; av[nf][1] *= corr1;
            av[nf][2] *= corr2; av[nf][3] *= corr2;
        }

#pragma unroll
        for (int ks2 = 0; ks2 < 8; ks2++) {
            uint32_t a0 = f2tf32(acc[ks2][0]);
            uint32_t a1 = f2tf32(acc[ks2][2]);
            uint32_t a2 = f2tf32(acc[ks2][1]);
            uint32_t a3 = f2tf32(acc[ks2][3]);
#pragma unroll
            for (int nf2 = 0; nf2 < 8; nf2++) {
                const float2 bv = *(const float2*)(Vs + (nf2 * 8 + g) * VS2
                                                   + ks2 * 8 + 2 * tg);
                mma_tf32(av[nf2], a0, a1, a2, a3,
                         __float_as_uint(bv.x), __float_as_uint(bv.y));
            }
        }
        __syncthreads();
    }

    const float inv1 = 1.f / rs1;
    const float inv2 = 1.f / rs2;
    float* AOb = g_AO + (size_t)b * N_ * C_;
    const int r1 = wid * 16 + g;
#pragma unroll
    for (int nf2 = 0; nf2 < 8; nf2++) {
#pragma unroll
        for (int e = 0; e < 4; e++) {
            int d = nf2 * 8 + 2 * tg + (e & 1);
            int rr = r1 + ((e >> 1) ? 8 : 0);
            float v = tf32f(av[nf2][e] * ((e >> 1) ? inv2 : inv1));
            int n = n0 + rr;
            unsigned lin = (unsigned)(h * HD + d) * NE + (unsigned)n;
            unsigned ne2 = lin / C_;
            unsigned cz  = lin - ne2 * C_;
            unsigned nf3 = ne2 * S_ + (unsigned)sP;
            AOb[(size_t)nf3 * C_ + cz] = v;
        }
    }
}

// ---------------- K6: BN finalize + residual + normalize (fused) ----------------
__global__ __launch_bounds__(256) void final_kernel(
    const float* __restrict__ x,
    const float* __restrict__ gamma,
    const float* __restrict__ beta,
    float* __restrict__ out)
{
    __shared__ float sS[8], sQ[8];
    __shared__ float sMu, sRs;
    const int t = threadIdx.x;
    const int bc = blockIdx.x;
    const int c = bc % C_;

    float s = g_bnS[(size_t)c * 256 + t];
    float q = g_bnQ[(size_t)c * 256 + t];
#pragma unroll
    for (int off = 16; off > 0; off >>= 1) {
        s += __shfl_xor_sync(0xffffffffu, s, off);
        q += __shfl_xor_sync(0xffffffffu, q, off);
    }
    if ((t & 31) == 0) { sS[t >> 5] = s; sQ[t >> 5] = q; }
    __syncthreads();
    if (t == 0) {
        float ss = ((sS[0] + sS[1]) + (sS[2] + sS[3])) + ((sS[4] + sS[5]) + (sS[6] + sS[7]));
        float qq = ((sQ[0] + sQ[1]) + (sQ[2] + sQ[3])) + ((sQ[4] + sQ[5]) + (sQ[6] + sQ[7]));
        float inv_n = 1.f / (float)(B_ * N_);
        float mu  = ss * inv_n;
        float var = qq * inv_n - mu * mu;
        sMu = mu;
        sRs = rsqrtf(var + EPS_);
    }
    __syncthreads();

    const float ga = gamma[c], be = beta[c], mu = sMu, rs = sRs;
    size_t base = (size_t)bc * N_ + t * 4;
    float4 v  = *(const float4*)(g_P + base);
    float4 xv = *(const float4*)(x + base);
    float4 r;
    r.x = xv.x + ga * (v.x - mu) * rs + be;
    r.y = xv.y + ga * (v.y - mu) * rs + be;
    r.z = xv.z + ga * (v.z - mu) * rs + be;
    r.w = xv.w + ga * (v.w - mu) * rs + be;
    *(float4*)(out + base) = r;
}

// ---------------- launch ----------------
extern "C" void kernel_launch(void* const* d_in, const int* in_sizes, int n_in,
                              void* d_out, int out_size)
{
    const float* x     = (const float*)d_in[0];
    const float* Wq    = (const float*)d_in[1];
    const float* Wk    = (const float*)d_in[2];
    const float* Wv    = (const float*)d_in[3];
    const float* Wpe   = (const float*)d_in[4];
    const float* Wproj = (const float*)d_in[5];
    const float* gamma = (const float*)d_in[6];
    const float* beta  = (const float*)d_in[7];
    float* out = (float*)d_out;

    static bool attr_set = false;
    if (!attr_set) {
        cudaFuncSetAttribute(qkv_mma, cudaFuncAttributeMaxDynamicSharedMemorySize,
                             GS_FLOATS * (int)sizeof(float));
        cudaFuncSetAttribute(proj_mma, cudaFuncAttributeMaxDynamicSharedMemorySize,
                             PS_FLOATS * (int)sizeof(float));
        cudaFuncSetAttribute(attn_flash, cudaFuncAttributeMaxDynamicSharedMemorySize,
                             ATT_FLOATS * (int)sizeof(float));
        attr_set = true;
    }

    prep_weights<<<(4 * C_ * C_) / 1024, 256>>>(Wq, Wk, Wv, Wproj);

    qkv_mma<<<dim3(N_ / 128, 9, B_), 256, GS_FLOATS * sizeof(float)>>>(x);

    dwconv_smem<<<B_ * C_, 256>>>(Wpe);

    attn_flash<<<dim3(4, NHEAD, 128), 128, ATT_FLOATS * sizeof(float)>>>();

    proj_mma<<<dim3(N_ / 128, C_ / 128, B_), 256, PS_FLOATS * sizeof(float)>>>();

    final_kernel<<<B_ * C_, 256>>>(x, gamma, beta, out);
}